// round 6
// baseline (speedup 1.0000x reference)
#include <cuda_runtime.h>
#include <cuda_bf16.h>

// 2x FIR upsample (upfirdn2d), separable [1,3,3,1]/4 tap, depthwise, fp32.
// Input (B*C, 128, 128) -> Output (B*C, 256, 256).
//
//   out[2y  ] = (1*x[y-1] + 3*x[y  ]) / 4   vertically, same horizontally
//   out[2y+1] = (3*x[y  ] + 1*x[y+1]) / 4
//
// Thread tx in [0,64) covers out cols 4tx..4tx+3 (input cols 2tx-1..2tx+2).
// Each thread computes 8 output rows (8t..8t+7) from 6 input rows (4t-1..4t+4).
// Halo input values come from neighbor lanes via warp shuffle; only warp-edge
// lanes issue predicated scalar loads. Warp stores are 512B contiguous .cs.

#define H_IN  128
#define W_IN  128
#define W_OUT 256

__device__ __forceinline__ void stcs4(float* p, float4 v) {
    asm volatile("st.global.cs.v4.f32 [%0], {%1,%2,%3,%4};"
                 :: "l"(p), "f"(v.x), "f"(v.y), "f"(v.z), "f"(v.w) : "memory");
}

__global__ __launch_bounds__(256) void upfir2x_kernel(
    const float* __restrict__ in, float* __restrict__ out)
{
    const int plane = blockIdx.z;
    const int tx = threadIdx.x;                            // 0..63 -> out cols 4tx..4tx+3
    const int t  = blockIdx.y * blockDim.y + threadIdx.y;  // 0..31 -> out rows 8t..8t+7
    const int lane = tx & 31;                              // warps contiguous in tx

    const float* src = in + (size_t)plane * (H_IN * W_IN);
    const int xc = 2 * tx;          // input col base; need cols xc-1 .. xc+2
    const int row0 = 4 * t - 1;     // input rows row0 .. row0+5

    // Per input row j (= input row row0+j): 4 horizontal taps (unnormalized).
    float h[6][4];
    #pragma unroll
    for (int j = 0; j < 6; j++) {
        const int row = row0 + j;
        float2 v = make_float2(0.f, 0.f);
        float pe = 0.f, ne = 0.f;       // edge-lane halo values
        if (row >= 0 && row < H_IN) {   // uniform across warp
            const float* r = src + row * W_IN;
            v = *reinterpret_cast<const float2*>(r + xc);   // coalesced 256B/warp
            if (lane == 0  && xc > 0)        pe = __ldg(r + xc - 1);
            if (lane == 31 && xc + 2 < W_IN) ne = __ldg(r + xc + 2);
        }
        float p = __shfl_up_sync(0xffffffffu, v.y, 1);
        float n = __shfl_down_sync(0xffffffffu, v.x, 1);
        if (lane == 0)  p = pe;
        if (lane == 31) n = ne;

        h[j][0] = fmaf(3.f, v.x, p);     // out col 4tx   : in[2tx-1] + 3*in[2tx]
        h[j][1] = fmaf(3.f, v.x, v.y);   // out col 4tx+1 : 3*in[2tx] + in[2tx+1]
        h[j][2] = fmaf(3.f, v.y, v.x);   // out col 4tx+2 : in[2tx] + 3*in[2tx+1]
        h[j][3] = fmaf(3.f, v.y, n);     // out col 4tx+3 : 3*in[2tx+1] + in[2tx+2]
    }

    // Vertical combine (unnormalized, /16 at end):
    //   8t+0 = 1*h[0] + 3*h[1]     8t+1 = 3*h[1] + 1*h[2]
    //   8t+2 = 1*h[1] + 3*h[2]     8t+3 = 3*h[2] + 1*h[3]
    //   8t+4 = 1*h[2] + 3*h[3]     8t+5 = 3*h[3] + 1*h[4]
    //   8t+6 = 1*h[3] + 3*h[4]     8t+7 = 3*h[4] + 1*h[5]
    // Closed form: jA = (i+1)>>1, jB = jA+1, wA = (i&1)?3:1, wB = 4-wA.
    const float s = 1.0f / 16.0f;
    float* dst = out + (size_t)plane * (W_OUT * W_OUT)
                     + (size_t)(8 * t) * W_OUT + tx * 4;

    #pragma unroll
    for (int i = 0; i < 8; i++) {
        const int jA = (i + 1) >> 1;          // 0,1,1,2,2,3,3,4
        const int jB = jA + 1;                // 1,2,2,3,3,4,4,5
        const float wA = (i & 1) ? 3.f : 1.f;
        const float wB = 4.f - wA;

        float4 o;
        o.x = (wA * h[jA][0] + wB * h[jB][0]) * s;
        o.y = (wA * h[jA][1] + wB * h[jB][1]) * s;
        o.z = (wA * h[jA][2] + wB * h[jB][2]) * s;
        o.w = (wA * h[jA][3] + wB * h[jB][3]) * s;
        stcs4(dst + (size_t)i * W_OUT, o);
    }
}

extern "C" void kernel_launch(void* const* d_in, const int* in_sizes, int n_in,
                              void* d_out, int out_size) {
    const float* x = (const float*)d_in[0];
    float* out = (float*)d_out;

    const int planes = in_sizes[0] / (H_IN * W_IN);   // B*C = 1024

    dim3 block(64, 4, 1);            // 256 threads: 64 col-quads x 4 row-groups
    dim3 grid(1, 32 / 4, planes);    // 8 row-group blocks x 1024 planes
    upfir2x_kernel<<<grid, block>>>(x, out);
}

// round 7
// speedup vs baseline: 1.0239x; 1.0239x over previous
#include <cuda_runtime.h>
#include <cuda_bf16.h>

// 2x FIR upsample (upfirdn2d), separable [1,3,3,1]/4 tap, depthwise, fp32.
// Input (B*C, 128, 128) -> Output (B*C, 256, 256).
//
//   out[2y  ] = (1*x[y-1] + 3*x[y  ]) / 4   vertically, same horizontally
//   out[2y+1] = (3*x[y  ] + 1*x[y+1]) / 4
//
// Thread tx in [0,64) covers out cols 4tx..4tx+3 (input cols 2tx-1..2tx+2).
// Each thread computes 4 output rows (4t..4t+3) from input rows 2t-1..2t+2.
// All 4 row loads are issued before any dependent math (front-batched MLP).
// Halos come from neighbor lanes via warp shuffle; warp-edge lanes use
// predicated scalar loads. Warp stores are 512B contiguous streaming (.cs).

#define H_IN  128
#define W_IN  128
#define W_OUT 256

__device__ __forceinline__ void stcs4(float* p, float4 v) {
    asm volatile("st.global.cs.v4.f32 [%0], {%1,%2,%3,%4};"
                 :: "l"(p), "f"(v.x), "f"(v.y), "f"(v.z), "f"(v.w) : "memory");
}

__global__ __launch_bounds__(512) void upfir2x_kernel(
    const float* __restrict__ in, float* __restrict__ out)
{
    const int plane = blockIdx.z;
    const int tx = threadIdx.x;                            // 0..63 -> out cols 4tx..4tx+3
    const int t  = blockIdx.y * blockDim.y + threadIdx.y;  // 0..63 -> out rows 4t..4t+3
    const int lane = tx & 31;                              // warps contiguous in tx

    const float* src = in + (size_t)plane * (H_IN * W_IN);
    const int xc = 2 * tx;          // input col base; need cols xc-1 .. xc+2
    const int row0 = 2 * t - 1;     // input rows row0 .. row0+3

    // ---- Phase 1: issue all loads (front-batched) ----
    float2 v[4];
    float pe[4], ne[4];
    #pragma unroll
    for (int j = 0; j < 4; j++) {
        const int row = row0 + j;
        v[j] = make_float2(0.f, 0.f);
        pe[j] = 0.f; ne[j] = 0.f;
        if (row >= 0 && row < H_IN) {          // warp-uniform predicate
            const float* r = src + row * W_IN;
            v[j] = *reinterpret_cast<const float2*>(r + xc);   // coalesced 256B/warp
            if (lane == 0  && xc > 0)        pe[j] = __ldg(r + xc - 1);
            if (lane == 31 && xc + 2 < W_IN) ne[j] = __ldg(r + xc + 2);
        }
    }

    // ---- Phase 2: shuffles + horizontal taps ----
    float h[4][4];
    #pragma unroll
    for (int j = 0; j < 4; j++) {
        float p = __shfl_up_sync(0xffffffffu, v[j].y, 1);
        float n = __shfl_down_sync(0xffffffffu, v[j].x, 1);
        if (lane == 0)  p = pe[j];
        if (lane == 31) n = ne[j];

        h[j][0] = fmaf(3.f, v[j].x, p);        // out col 4tx   : in[2tx-1] + 3*in[2tx]
        h[j][1] = fmaf(3.f, v[j].x, v[j].y);   // out col 4tx+1 : 3*in[2tx] + in[2tx+1]
        h[j][2] = fmaf(3.f, v[j].y, v[j].x);   // out col 4tx+2 : in[2tx] + 3*in[2tx+1]
        h[j][3] = fmaf(3.f, v[j].y, n);        // out col 4tx+3 : 3*in[2tx+1] + in[2tx+2]
    }

    // ---- Phase 3: vertical combine (/16 at end) ----
    //   4t   = 1*h[0] + 3*h[1]
    //   4t+1 = 3*h[1] + 1*h[2]
    //   4t+2 = 1*h[1] + 3*h[2]
    //   4t+3 = 3*h[2] + 1*h[3]
    const float s = 1.0f / 16.0f;
    float* dst = out + (size_t)plane * (W_OUT * W_OUT)
                     + (size_t)(4 * t) * W_OUT + tx * 4;

    {
        float4 o;
        o.x = fmaf(3.f, h[1][0], h[0][0]) * s;
        o.y = fmaf(3.f, h[1][1], h[0][1]) * s;
        o.z = fmaf(3.f, h[1][2], h[0][2]) * s;
        o.w = fmaf(3.f, h[1][3], h[0][3]) * s;
        stcs4(dst, o);
    }
    {
        float4 o;
        o.x = fmaf(3.f, h[1][0], h[2][0]) * s;
        o.y = fmaf(3.f, h[1][1], h[2][1]) * s;
        o.z = fmaf(3.f, h[1][2], h[2][2]) * s;
        o.w = fmaf(3.f, h[1][3], h[2][3]) * s;
        stcs4(dst + W_OUT, o);
    }
    {
        float4 o;
        o.x = fmaf(3.f, h[2][0], h[1][0]) * s;
        o.y = fmaf(3.f, h[2][1], h[1][1]) * s;
        o.z = fmaf(3.f, h[2][2], h[1][2]) * s;
        o.w = fmaf(3.f, h[2][3], h[1][3]) * s;
        stcs4(dst + 2 * W_OUT, o);
    }
    {
        float4 o;
        o.x = fmaf(3.f, h[2][0], h[3][0]) * s;
        o.y = fmaf(3.f, h[2][1], h[3][1]) * s;
        o.z = fmaf(3.f, h[2][2], h[3][2]) * s;
        o.w = fmaf(3.f, h[2][3], h[3][3]) * s;
        stcs4(dst + 3 * W_OUT, o);
    }
}

extern "C" void kernel_launch(void* const* d_in, const int* in_sizes, int n_in,
                              void* d_out, int out_size) {
    const float* x = (const float*)d_in[0];
    float* out = (float*)d_out;

    const int planes = in_sizes[0] / (H_IN * W_IN);   // B*C = 1024

    dim3 block(64, 8, 1);            // 512 threads: 64 col-quads x 8 row-groups
    dim3 grid(1, 64 / 8, planes);    // 8 row-group blocks x 1024 planes
    upfir2x_kernel<<<grid, block>>>(x, out);
}

// round 8
// speedup vs baseline: 1.0391x; 1.0148x over previous
#include <cuda_runtime.h>
#include <cuda_bf16.h>

// 2x FIR upsample (upfirdn2d), separable [1,3,3,1]/4 tap, depthwise, fp32.
// Input (B*C, 128, 128) -> Output (B*C, 256, 256).
//
//   out[2y  ] = (1*x[y-1] + 3*x[y  ]) / 4   vertically, same horizontally
//   out[2y+1] = (3*x[y  ] + 1*x[y+1]) / 4
//
// Thread tx in [0,64) covers out cols 4tx..4tx+3 (input cols 2tx-1..2tx+2).
// Each thread computes 4 output rows (4t..4t+3) from input rows 2t-1..2t+2.
// All 4 row loads are issued before any dependent math (front-batched MLP).
// Halos come from neighbor lanes via warp shuffle; warp-edge lanes use
// predicated scalar loads. Warp stores are 512B contiguous streaming (.cs).

#define H_IN  128
#define W_IN  128
#define W_OUT 256

__device__ __forceinline__ void stcs4(float* p, float4 v) {
    asm volatile("st.global.cs.v4.f32 [%0], {%1,%2,%3,%4};"
                 :: "l"(p), "f"(v.x), "f"(v.y), "f"(v.z), "f"(v.w) : "memory");
}

__global__ __launch_bounds__(256) void upfir2x_kernel(
    const float* __restrict__ in, float* __restrict__ out)
{
    const int plane = blockIdx.z;
    const int tx = threadIdx.x;                            // 0..63 -> out cols 4tx..4tx+3
    const int t  = blockIdx.y * blockDim.y + threadIdx.y;  // 0..63 -> out rows 4t..4t+3
    const int lane = tx & 31;                              // warps contiguous in tx

    const float* src = in + (size_t)plane * (H_IN * W_IN);
    const int xc = 2 * tx;          // input col base; need cols xc-1 .. xc+2
    const int row0 = 2 * t - 1;     // input rows row0 .. row0+3

    // ---- Phase 1: issue all loads (front-batched, MLP=4) ----
    float2 v[4];
    float pe[4], ne[4];
    #pragma unroll
    for (int j = 0; j < 4; j++) {
        const int row = row0 + j;
        v[j] = make_float2(0.f, 0.f);
        pe[j] = 0.f; ne[j] = 0.f;
        if (row >= 0 && row < H_IN) {          // warp-uniform predicate
            const float* r = src + row * W_IN;
            v[j] = *reinterpret_cast<const float2*>(r + xc);   // coalesced 256B/warp
            if (lane == 0  && xc > 0)        pe[j] = __ldg(r + xc - 1);
            if (lane == 31 && xc + 2 < W_IN) ne[j] = __ldg(r + xc + 2);
        }
    }

    // ---- Phase 2: shuffles + horizontal taps (unnormalized) ----
    float h[4][4];
    #pragma unroll
    for (int j = 0; j < 4; j++) {
        float p = __shfl_up_sync(0xffffffffu, v[j].y, 1);
        float n = __shfl_down_sync(0xffffffffu, v[j].x, 1);
        if (lane == 0)  p = pe[j];
        if (lane == 31) n = ne[j];

        h[j][0] = fmaf(3.f, v[j].x, p);        // out col 4tx   : in[2tx-1] + 3*in[2tx]
        h[j][1] = fmaf(3.f, v[j].x, v[j].y);   // out col 4tx+1 : 3*in[2tx] + in[2tx+1]
        h[j][2] = fmaf(3.f, v[j].y, v[j].x);   // out col 4tx+2 : in[2tx] + 3*in[2tx+1]
        h[j][3] = fmaf(3.f, v[j].y, n);        // out col 4tx+3 : 3*in[2tx+1] + in[2tx+2]
    }

    // ---- Phase 3: vertical combine (/16 at end) ----
    //   4t   = 1*h[0] + 3*h[1]
    //   4t+1 = 3*h[1] + 1*h[2]
    //   4t+2 = 1*h[1] + 3*h[2]
    //   4t+3 = 3*h[2] + 1*h[3]
    const float s = 1.0f / 16.0f;
    float* dst = out + (size_t)plane * (W_OUT * W_OUT)
                     + (size_t)(4 * t) * W_OUT + tx * 4;

    {
        float4 o;
        o.x = fmaf(3.f, h[1][0], h[0][0]) * s;
        o.y = fmaf(3.f, h[1][1], h[0][1]) * s;
        o.z = fmaf(3.f, h[1][2], h[0][2]) * s;
        o.w = fmaf(3.f, h[1][3], h[0][3]) * s;
        stcs4(dst, o);
    }
    {
        float4 o;
        o.x = fmaf(3.f, h[1][0], h[2][0]) * s;
        o.y = fmaf(3.f, h[1][1], h[2][1]) * s;
        o.z = fmaf(3.f, h[1][2], h[2][2]) * s;
        o.w = fmaf(3.f, h[1][3], h[2][3]) * s;
        stcs4(dst + W_OUT, o);
    }
    {
        float4 o;
        o.x = fmaf(3.f, h[2][0], h[1][0]) * s;
        o.y = fmaf(3.f, h[2][1], h[1][1]) * s;
        o.z = fmaf(3.f, h[2][2], h[1][2]) * s;
        o.w = fmaf(3.f, h[2][3], h[1][3]) * s;
        stcs4(dst + 2 * W_OUT, o);
    }
    {
        float4 o;
        o.x = fmaf(3.f, h[2][0], h[3][0]) * s;
        o.y = fmaf(3.f, h[2][1], h[3][1]) * s;
        o.z = fmaf(3.f, h[2][2], h[3][2]) * s;
        o.w = fmaf(3.f, h[2][3], h[3][3]) * s;
        stcs4(dst + 3 * W_OUT, o);
    }
}

extern "C" void kernel_launch(void* const* d_in, const int* in_sizes, int n_in,
                              void* d_out, int out_size) {
    const float* x = (const float*)d_in[0];
    float* out = (float*)d_out;

    const int planes = in_sizes[0] / (H_IN * W_IN);   // B*C = 1024

    dim3 block(64, 4, 1);            // 256 threads: 64 col-quads x 4 row-groups
    dim3 grid(1, 64 / 4, planes);    // 16 row-group blocks x 1024 planes
    upfir2x_kernel<<<grid, block>>>(x, out);
}